// round 11
// baseline (speedup 1.0000x reference)
#include <cuda_runtime.h>

// ---------------------------------------------------------------------------
// Multigrid F-cycle, 4096x4096, t=4 iterations — ONE persistent kernel.
//   296 blocks x 512 threads, guaranteed co-resident (launch_bounds(512,2)).
//   Phase D: v -> r1..r7 (tile-local, xor-shuffle halos)   [1024 tiles]
//   Phase E: r7 -> ... -> e1                               [1024 tiles]
//   Phase F: out = -edgestencil(v - prolong(e1))           [flat stride]
//   Grid barriers: atomic sense-reversing + __threadfence (CCTL.IVALL
//   invalidates L1 on both release and acquire sides).
// ---------------------------------------------------------------------------

#define N0 4096
#define CW 0.05f
#define NBLK 296
#define NTHR 512

static __device__ float g_v [N0 * N0];
static __device__ float g_r1[2048 * 2048];
static __device__ float g_e1[2048 * 2048];
static __device__ float g_r2[1024 * 1024];
static __device__ float g_r3[ 512 *  512];
static __device__ float g_r4[ 256 *  256];
static __device__ float g_r5[ 128 *  128];
static __device__ float g_r6[  64 *   64];
static __device__ float g_r7[  32 *   32];

// grid barrier state (returns to initial value after every full run)
static __device__ volatile unsigned g_gen = 0;
static __device__ unsigned g_cnt = 0;

static __device__ __forceinline__ void gsync() {
    __syncthreads();
    if (threadIdx.x == 0) {
        __threadfence();                       // release: writes -> L2, L1 inval
        unsigned gen = g_gen;
        unsigned old = atomicAdd(&g_cnt, 1);
        if (old == NBLK - 1) {
            g_cnt = 0;                         // safe: no arrivals until gen bump
            __threadfence();
            g_gen = gen + 1;
        } else {
            while (g_gen == gen) { }
            __threadfence();                   // acquire: invalidate stale L1
        }
    }
    __syncthreads();
}

static __device__ __forceinline__ void load8(const float* __restrict__ v,
                                             int yy, int x0, float* R) {
    const float4* p = (const float4*)(v + (size_t)yy * N0 + x0);
    float4 a = __ldg(p), b = __ldg(p + 1);
    R[0] = a.x; R[1] = a.y; R[2] = a.z; R[3] = a.w;
    R[4] = b.x; R[5] = b.y; R[6] = b.z; R[7] = b.w;
}

template<int SA, int NB, int SB, int WB>
static __device__ __forceinline__ void restr_step(const float* sA, float* sB,
                                                  float* __restrict__ g,
                                                  int bx, int by, int tid) {
    #pragma unroll 1
    for (int idx = tid; idx < NB * NB; idx += NTHR) {
        int I = idx / NB, J = idx - I * NB;
        const float* p = sA + (2 * I) * SA + 2 * J;
        float x = 0.25f * (p[0] + p[1] + p[SA] + p[SA + 1]);
        if (NB > 1) sB[I * SB + J] = x;
        g[(by * NB + I) * WB + (bx * NB + J)] = x;
    }
}

static __device__ __forceinline__ float4 smooth_quad(
    const float* A, const float* B, const float* C, const float* D,
    float hlB, float hlC, float hrB, float hrC) {
    float4 o;
    float* op = (float*)&o;
    #pragma unroll
    for (int j = 0; j < 4; ++j) {
        float c00 = B[2*j], c01 = B[2*j+1], c10 = C[2*j], c11 = C[2*j+1];
        float t0  = A[2*j], t1  = A[2*j+1], b0  = D[2*j], b1  = D[2*j+1];
        float l0 = j ? B[2*j-1] : hlB;
        float l1 = j ? C[2*j-1] : hlC;
        float q0 = (j < 3) ? B[2*j+2] : hrB;
        float q1 = (j < 3) ? C[2*j+2] : hrC;
        float s = (c00 + c01 + c10 + c11)
                + CW * ((t0 - c10) + (t1 - c11) + (c00 - b0) + (c01 - b1))
                + CW * ((l0 - c01) + (c00 - q0) + (l1 - c11) + (c10 - q1));
        op[j] = 0.25f * s;
    }
    return o;
}

// ---------------------------------------------------------------------------
// Phase D: one 64x64 r1 tile (identical to proven k_down body)
// ---------------------------------------------------------------------------
static __device__ void phase_down(const float* __restrict__ v, float* SM,
                                  int bx, int by, int tid) {
    float* s1 = SM;                 // 64*68 = 4352
    float* s2 = SM + 4352;          // 32*36 = 1152
    float* s3 = SM + 5504;          // 16*20 =  320
    float* s4 = SM + 5824;          //  8*12 =   96
    float* s5 = SM + 5920;          //  4* 8 =   32
    float* s6 = SM + 5952;          //  2* 4 =    8

    int Jt = tid & 15, It = tid >> 4;
    int x0 = (bx << 7) + (Jt << 3);
    int ybase = (by << 7) + (It << 2);
    bool leftEdge = (Jt == 0), rightEdge = (Jt == 15);
    bool evenIt = ((It & 1) == 0);
    int xl = max(x0 - 1, 0), xr = min(x0 + 8, N0 - 1);

    float A[8], B[8], C[8], D[8], E[8], F[8];
    load8(v, ybase,     x0, B);
    load8(v, ybase + 1, x0, C);
    load8(v, ybase + 2, x0, D);
    load8(v, ybase + 3, x0, E);
    if (evenIt) load8(v, max(ybase - 1, 0),      x0, A);
    else        load8(v, min(ybase + 4, N0 - 1), x0, F);

    float elB = 0.f, elC = 0.f, elD = 0.f, elE = 0.f;
    float erB = 0.f, erC = 0.f, erD = 0.f, erE = 0.f;
    if (leftEdge) {
        elB = __ldg(v + (size_t)(ybase    ) * N0 + xl);
        elC = __ldg(v + (size_t)(ybase + 1) * N0 + xl);
        elD = __ldg(v + (size_t)(ybase + 2) * N0 + xl);
        elE = __ldg(v + (size_t)(ybase + 3) * N0 + xl);
    }
    if (rightEdge) {
        erB = __ldg(v + (size_t)(ybase    ) * N0 + xr);
        erC = __ldg(v + (size_t)(ybase + 1) * N0 + xr);
        erD = __ldg(v + (size_t)(ybase + 2) * N0 + xr);
        erE = __ldg(v + (size_t)(ybase + 3) * N0 + xr);
    }

    #pragma unroll
    for (int i = 0; i < 8; ++i) {
        float pb = __shfl_xor_sync(0xffffffffu, B[i], 16);
        float pe = __shfl_xor_sync(0xffffffffu, E[i], 16);
        if (evenIt) F[i] = pb;
        else        A[i] = pe;
    }

    float hlB = __shfl_up_sync(0xffffffffu, B[7], 1);
    float hlC = __shfl_up_sync(0xffffffffu, C[7], 1);
    float hlD = __shfl_up_sync(0xffffffffu, D[7], 1);
    float hlE = __shfl_up_sync(0xffffffffu, E[7], 1);
    float hrB = __shfl_down_sync(0xffffffffu, B[0], 1);
    float hrC = __shfl_down_sync(0xffffffffu, C[0], 1);
    float hrD = __shfl_down_sync(0xffffffffu, D[0], 1);
    float hrE = __shfl_down_sync(0xffffffffu, E[0], 1);
    if (leftEdge)  { hlB = elB; hlC = elC; hlD = elD; hlE = elE; }
    if (rightEdge) { hrB = erB; hrC = erC; hrD = erD; hrE = erE; }

    float4 o0 = smooth_quad(A, B, C, D, hlB, hlC, hrB, hrC);
    float4 o1 = smooth_quad(C, D, E, F, hlD, hlE, hrD, hrE);

    int Ir0 = (by << 6) + (It << 1);
    *(float4*)(g_r1 + (size_t)Ir0 * 2048 + (bx << 6) + (Jt << 2)) = o0;
    *(float4*)(g_r1 + (size_t)(Ir0 + 1) * 2048 + (bx << 6) + (Jt << 2)) = o1;
    *(float4*)(s1 + ((It << 1)    ) * 68 + (Jt << 2)) = o0;
    *(float4*)(s1 + ((It << 1) + 1) * 68 + (Jt << 2)) = o1;
    __syncthreads();

    restr_step<68, 32, 36, 1024>(s1, s2, g_r2, bx, by, tid); __syncthreads();
    restr_step<36, 16, 20,  512>(s2, s3, g_r3, bx, by, tid); __syncthreads();
    restr_step<20,  8, 12,  256>(s3, s4, g_r4, bx, by, tid); __syncthreads();
    restr_step<12,  4,  8,  128>(s4, s5, g_r5, bx, by, tid); __syncthreads();
    restr_step< 8,  2,  4,   64>(s5, s6, g_r6, bx, by, tid); __syncthreads();
    restr_step< 4,  1,  1,   32>(s6, s6, g_r7, bx, by, tid); __syncthreads();
}

// ---------------------------------------------------------------------------
template<int TC, int NL>
static __device__ __forceinline__ void correct_level(const float* __restrict__ rL,
                                                     const float* par, float* dst,
                                                     int bx, int by, int tid) {
    const int T  = TC + 2;
    const int TP = TC / 2 + 2;
    const int Or = by * TC - 1, Oc = bx * TC - 1;
    const int Pr = by * (TC / 2) - 1, Pc = bx * (TC / 2) - 1;
    #pragma unroll 1
    for (int idx = tid; idx < T * T; idx += NTHR) {
        int Ii = idx / T, Jj = idx - Ii * T;
        int I = Or + Ii, J = Oc + Jj;
        float e = 0.0f;
        if (I >= 0 && I < NL && J >= 0 && J < NL) {
            int pc = (J >> 1) - Pc;
            int pr = (I >> 1) - Pr;
            float up = (I > 0)      ? par[(((I - 1) >> 1) - Pr) * TP + pc] : 0.0f;
            float dn = (I < NL - 1) ? par[(((I + 1) >> 1) - Pr) * TP + pc] : 0.0f;
            float lf = (J > 0)      ? par[pr * TP + (((J - 1) >> 1) - Pc)] : 0.0f;
            float rt = (J < NL - 1) ? par[pr * TP + (((J + 1) >> 1) - Pc)] : 0.0f;
            e = __ldg(rL + I * NL + J) - CW * (up - dn) - CW * (lf - rt);
        }
        dst[idx] = e;
    }
}

// ---------------------------------------------------------------------------
// Phase E: one 64x64 e1 tile (identical to proven k_e1 body)
// ---------------------------------------------------------------------------
static __device__ void phase_e1(float* SM, int bx, int by, int tid) {
    float* sr7 = SM;                // 1024
    float* s8  = SM + 1024;         //  256
    float* s9  = SM + 1280;         //   64
    float* e8s = SM + 1344;         //  256
    float* se7 = SM + 1600;         //    9
    float* se6 = SM + 1612;         //   16
    float* se5 = SM + 1628;         //   36
    float* se4 = SM + 1664;         //  100
    float* se3 = SM + 1764;         //  324
    float* se2 = SM + 2088;         // 1156 -> 3244 total

    if (tid < 256) ((float4*)sr7)[tid] = __ldg((const float4*)g_r7 + tid);
    __syncthreads();
    if (tid < 256) {
        int I = tid >> 4, J = tid & 15;
        const float* p = sr7 + (2 * I) * 32 + 2 * J;
        s8[tid] = 0.25f * (p[0] + p[1] + p[32] + p[33]);
    }
    __syncthreads();
    if (tid < 64) {
        int I = tid >> 3, J = tid & 7;
        const float* p = s8 + (2 * I) * 16 + 2 * J;
        s9[tid] = 0.25f * (p[0] + p[1] + p[16] + p[17]);
    }
    __syncthreads();
    if (tid < 256) {
        int I = tid >> 4, J = tid & 15;
        float up = (I > 0)  ? s9[((I - 1) >> 1) * 8 + (J >> 1)] : 0.0f;
        float dn = (I < 15) ? s9[((I + 1) >> 1) * 8 + (J >> 1)] : 0.0f;
        float lf = (J > 0)  ? s9[(I >> 1) * 8 + ((J - 1) >> 1)] : 0.0f;
        float rt = (J < 15) ? s9[(I >> 1) * 8 + ((J + 1) >> 1)] : 0.0f;
        e8s[tid] = s8[tid] - CW * (up - dn) - CW * (lf - rt);
    }
    __syncthreads();
    if (tid < 9) {
        int I = by - 1 + tid / 3, J = bx - 1 + tid % 3;
        float e = 0.0f;
        if (I >= 0 && I < 32 && J >= 0 && J < 32) {
            float up = (I > 0)  ? e8s[((I - 1) >> 1) * 16 + (J >> 1)] : 0.0f;
            float dn = (I < 31) ? e8s[((I + 1) >> 1) * 16 + (J >> 1)] : 0.0f;
            float lf = (J > 0)  ? e8s[(I >> 1) * 16 + ((J - 1) >> 1)] : 0.0f;
            float rt = (J < 31) ? e8s[(I >> 1) * 16 + ((J + 1) >> 1)] : 0.0f;
            e = sr7[I * 32 + J] - CW * (up - dn) - CW * (lf - rt);
        }
        se7[tid] = e;
    }
    __syncthreads();

    correct_level< 2,   64>(g_r6, se7, se6, bx, by, tid); __syncthreads();
    correct_level< 4,  128>(g_r5, se6, se5, bx, by, tid); __syncthreads();
    correct_level< 8,  256>(g_r4, se5, se4, bx, by, tid); __syncthreads();
    correct_level<16,  512>(g_r3, se4, se3, bx, by, tid); __syncthreads();
    correct_level<32, 1024>(g_r2, se3, se2, bx, by, tid); __syncthreads();

    const int Pr = by * 32 - 1, Pc = bx * 32 - 1;
    #pragma unroll
    for (int t0 = 0; t0 < 1024; t0 += NTHR) {
        int t = t0 + tid;
        int Ii = t >> 4, Jq = t & 15;
        int I  = (by << 6) + Ii;
        int J0 = (bx << 6) + (Jq << 2);
        float4 r = __ldg((const float4*)(g_r1 + (size_t)I * 2048 + J0));

        int pc0 = (J0 >> 1) - Pc;
        int mr  = (I >> 1) - Pr;
        int ur  = ((I - 1) >> 1) - Pr;
        int dr  = ((I + 1) >> 1) - Pr;
        const float* Sm = se2 + mr * 34;

        float u0 = 0.0f, u1 = 0.0f, d0 = 0.0f, d1 = 0.0f;
        if (I > 0)    { u0 = se2[ur * 34 + pc0]; u1 = se2[ur * 34 + pc0 + 1]; }
        if (I < 2047) { d0 = se2[dr * 34 + pc0]; d1 = se2[dr * 34 + pc0 + 1]; }
        float m_1 = (J0 > 0)        ? Sm[pc0 - 1] : 0.0f;
        float m0  = Sm[pc0];
        float m1  = Sm[pc0 + 1];
        float m2  = (J0 + 3 < 2047) ? Sm[pc0 + 2] : 0.0f;

        float4 e;
        e.x = r.x - CW * (u0 - d0) - CW * (m_1 - m0);
        e.y = r.y - CW * (u0 - d0) - CW * (m0  - m1);
        e.z = r.z - CW * (u1 - d1) - CW * (m0  - m1);
        e.w = r.w - CW * (u1 - d1) - CW * (m1  - m2);
        *(float4*)(g_e1 + (size_t)I * 2048 + J0) = e;
    }
    __syncthreads();
}

// ---------------------------------------------------------------------------
// Phase F: streaming final update, flat grid-stride over 2^22 float4 outputs
// ---------------------------------------------------------------------------
static __device__ void phase_final(const float* __restrict__ v,
                                   float* __restrict__ out, int bid, int tid) {
    const float* e1 = g_e1;
    #pragma unroll 1
    for (int idx = bid * NTHR + tid; idx < (1 << 22); idx += NBLK * NTHR) {
        int y = idx >> 10;
        int x = (idx & 1023) << 2;
        int ym = max(y - 1, 0), yp = min(y + 1, N0 - 1);
        int xl = max(x - 1, 0), xr = min(x + 4, N0 - 1);
        int xc = x >> 1;

        float4 top = __ldg((const float4*)(v + (size_t)ym * N0 + x));
        float4 mid = __ldg((const float4*)(v + (size_t)y  * N0 + x));
        float4 bot = __ldg((const float4*)(v + (size_t)yp * N0 + x));
        float  lf  = __ldg(v + (size_t)y * N0 + xl);
        float  rt  = __ldg(v + (size_t)y * N0 + xr);

        const float* et = e1 + (ym >> 1) * 2048;
        const float* em = e1 + (y  >> 1) * 2048;
        const float* eb = e1 + (yp >> 1) * 2048;
        float2 e_t = __ldg((const float2*)(et + xc));
        float2 e_m = __ldg((const float2*)(em + xc));
        float2 e_b = __ldg((const float2*)(eb + xc));
        float  emL = __ldg(em + (xl >> 1));
        float  emR = __ldg(em + (xr >> 1));

        float4 o;
        o.x = -CW * ((top.x - e_t.x) - (bot.x - e_b.x)) - CW * ((lf    - emL)   - (mid.y - e_m.x));
        o.y = -CW * ((top.y - e_t.x) - (bot.y - e_b.x)) - CW * ((mid.x - e_m.x) - (mid.z - e_m.y));
        o.z = -CW * ((top.z - e_t.y) - (bot.z - e_b.y)) - CW * ((mid.y - e_m.x) - (mid.w - e_m.y));
        o.w = -CW * ((top.w - e_t.y) - (bot.w - e_b.y)) - CW * ((mid.z - e_m.y) - (rt    - emR));
        *(float4*)(out + (size_t)y * N0 + x) = o;
    }
}

// ---------------------------------------------------------------------------
// Megakernel: all 4 iterations, 11 grid barriers, 1 launch.
// ---------------------------------------------------------------------------
__global__ void __launch_bounds__(NTHR, 2) k_mega(const float* __restrict__ u,
                                                  float* __restrict__ out) {
    __shared__ __align__(16) float SM[6000];
    int tid = threadIdx.x;
    int bid = blockIdx.x;

    #pragma unroll 1
    for (int it = 0; it < 4; ++it) {
        const float* v = (it == 0) ? u : ((it == 2) ? (const float*)out
                                                    : (const float*)g_v);
        float* w = (it & 1) ? out : g_v;

        #pragma unroll 1
        for (int t = bid; t < 1024; t += NBLK)
            phase_down(v, SM, t & 31, t >> 5, tid);
        gsync();

        #pragma unroll 1
        for (int t = bid; t < 1024; t += NBLK)
            phase_e1(SM, t & 31, t >> 5, tid);
        gsync();

        phase_final(v, w, bid, tid);
        if (it < 3) gsync();
    }
}

// ---------------------------------------------------------------------------
extern "C" void kernel_launch(void* const* d_in, const int* in_sizes, int n_in,
                              void* d_out, int out_size) {
    const float* u = (const float*)d_in[0];
    float* out = (float*)d_out;
    k_mega<<<NBLK, NTHR>>>(u, out);
}

// round 12
// speedup vs baseline: 1.2878x; 1.2878x over previous
#include <cuda_runtime.h>

// ---------------------------------------------------------------------------
// Multigrid F-cycle, 4096x4096, t=4 iterations, 3 kernels per iteration.
//   CW = DT/DX/2 = 0.05, DIAG = 1.
//   k_down : v -> r1..r7 (hoisted row loads for MLP; shuffle halos)
//   k_e1   : r7 -> r8,r9 -> e8 -> e7(3x3) -> e6..e2 smem -> e1 global
//   k_final: out = -edgestencil(v - prolong(e1));  v loads use __ldcs
//            (evict-first: v is dead after this kernel, keep out in L2)
// ---------------------------------------------------------------------------

#define N0 4096
#define CW 0.05f

static __device__ float g_v [N0 * N0];
static __device__ float g_r1[2048 * 2048];
static __device__ float g_e1[2048 * 2048];
static __device__ float g_r2[1024 * 1024];
static __device__ float g_r3[ 512 *  512];
static __device__ float g_r4[ 256 *  256];
static __device__ float g_r5[ 128 *  128];
static __device__ float g_r6[  64 *   64];
static __device__ float g_r7[  32 *   32];

static __device__ __forceinline__ void load8(const float* __restrict__ v,
                                             int yy, int x0, float* R) {
    const float4* p = (const float4*)(v + (size_t)yy * N0 + x0);
    float4 a = __ldg(p), b = __ldg(p + 1);
    R[0] = a.x; R[1] = a.y; R[2] = a.z; R[3] = a.w;
    R[4] = b.x; R[5] = b.y; R[6] = b.z; R[7] = b.w;
}

// ---------------------------------------------------------------------------
template<int NA, int SA, int NB, int SB, int WB, int NT>
static __device__ __forceinline__ void restr_step(const float* sA, float* sB,
                                                  float* __restrict__ g,
                                                  int bx, int by, int tid) {
    #pragma unroll 1
    for (int idx = tid; idx < NB * NB; idx += NT) {
        int I = idx / NB, J = idx - I * NB;
        const float* p = sA + (2 * I) * SA + 2 * J;
        float x = 0.25f * (p[0] + p[1] + p[SA] + p[SA + 1]);
        if (NB > 1) sB[I * SB + J] = x;
        g[(by * NB + I) * WB + (bx * NB + J)] = x;
    }
}

// one fused smooth+restrict output quad from 4 row-registers
static __device__ __forceinline__ float4 smooth_quad(
    const float* A, const float* B, const float* C, const float* D,
    float hlB, float hlC, float hrB, float hrC) {
    float4 o;
    float* op = (float*)&o;
    #pragma unroll
    for (int j = 0; j < 4; ++j) {
        float c00 = B[2*j], c01 = B[2*j+1], c10 = C[2*j], c11 = C[2*j+1];
        float t0  = A[2*j], t1  = A[2*j+1], b0  = D[2*j], b1  = D[2*j+1];
        float l0 = j ? B[2*j-1] : hlB;
        float l1 = j ? C[2*j-1] : hlC;
        float q0 = (j < 3) ? B[2*j+2] : hrB;
        float q1 = (j < 3) ? C[2*j+2] : hrC;
        float s = (c00 + c01 + c10 + c11)
                + CW * ((t0 - c10) + (t1 - c11) + (c00 - b0) + (c01 - b1))
                + CW * ((l0 - c01) + (c00 - q0) + (l1 - c11) + (c10 - q1));
        op[j] = 0.25f * s;
    }
    return o;
}

// ---------------------------------------------------------------------------
// k_down: 64x64 r1 tile per block, 512 threads. Each thread: 2 r1 rows x 4
// r1 cols from 6 v rows x 8 cols, ALL loads hoisted upfront (max MLP).
// Horizontal halos via warp shuffle; strip-edge lanes load from global.
// ---------------------------------------------------------------------------
__global__ __launch_bounds__(512) void k_down(const float* __restrict__ v) {
    __shared__ __align__(16) float s1[64 * 68];
    __shared__ float s2[32 * 36];
    __shared__ float s3[16 * 20];
    __shared__ float s4[ 8 * 12];
    __shared__ float s5[ 4 *  8];
    __shared__ float s6[ 2 *  4];

    int tid = threadIdx.x;
    int bx = blockIdx.x, by = blockIdx.y;
    int Jt = tid & 15, It = tid >> 4;
    int x0 = (bx << 7) + (Jt << 3);
    int ybase = (by << 7) + (It << 2);
    bool leftEdge = (Jt == 0), rightEdge = (Jt == 15);
    int xl = max(x0 - 1, 0), xr = min(x0 + 8, N0 - 1);

    float A[8], B[8], C[8], D[8], E[8], F[8];
    load8(v, max(ybase - 1, 0),  x0, A);
    load8(v, ybase,              x0, B);
    load8(v, ybase + 1,          x0, C);
    load8(v, ybase + 2,          x0, D);
    load8(v, ybase + 3,          x0, E);
    load8(v, min(ybase + 4, N0 - 1), x0, F);

    float elB = 0.f, elC = 0.f, elD = 0.f, elE = 0.f;
    float erB = 0.f, erC = 0.f, erD = 0.f, erE = 0.f;
    if (leftEdge) {
        elB = __ldg(v + (size_t)(ybase    ) * N0 + xl);
        elC = __ldg(v + (size_t)(ybase + 1) * N0 + xl);
        elD = __ldg(v + (size_t)(ybase + 2) * N0 + xl);
        elE = __ldg(v + (size_t)(ybase + 3) * N0 + xl);
    }
    if (rightEdge) {
        erB = __ldg(v + (size_t)(ybase    ) * N0 + xr);
        erC = __ldg(v + (size_t)(ybase + 1) * N0 + xr);
        erD = __ldg(v + (size_t)(ybase + 2) * N0 + xr);
        erE = __ldg(v + (size_t)(ybase + 3) * N0 + xr);
    }

    float hlB = __shfl_up_sync(0xffffffffu, B[7], 1);
    float hlC = __shfl_up_sync(0xffffffffu, C[7], 1);
    float hlD = __shfl_up_sync(0xffffffffu, D[7], 1);
    float hlE = __shfl_up_sync(0xffffffffu, E[7], 1);
    float hrB = __shfl_down_sync(0xffffffffu, B[0], 1);
    float hrC = __shfl_down_sync(0xffffffffu, C[0], 1);
    float hrD = __shfl_down_sync(0xffffffffu, D[0], 1);
    float hrE = __shfl_down_sync(0xffffffffu, E[0], 1);
    if (leftEdge)  { hlB = elB; hlC = elC; hlD = elD; hlE = elE; }
    if (rightEdge) { hrB = erB; hrC = erC; hrD = erD; hrE = erE; }

    float4 o0 = smooth_quad(A, B, C, D, hlB, hlC, hrB, hrC);
    float4 o1 = smooth_quad(C, D, E, F, hlD, hlE, hrD, hrE);

    int Ir0 = (by << 6) + (It << 1);
    *(float4*)(g_r1 + (size_t)Ir0 * 2048 + (bx << 6) + (Jt << 2)) = o0;
    *(float4*)(g_r1 + (size_t)(Ir0 + 1) * 2048 + (bx << 6) + (Jt << 2)) = o1;
    *(float4*)(s1 + ((It << 1)    ) * 68 + (Jt << 2)) = o0;
    *(float4*)(s1 + ((It << 1) + 1) * 68 + (Jt << 2)) = o1;
    __syncthreads();

    restr_step<64, 68, 32, 36, 1024, 512>(s1, s2, g_r2, bx, by, tid); __syncthreads();
    restr_step<32, 36, 16, 20,  512, 512>(s2, s3, g_r3, bx, by, tid); __syncthreads();
    restr_step<16, 20,  8, 12,  256, 512>(s3, s4, g_r4, bx, by, tid); __syncthreads();
    restr_step< 8, 12,  4,  8,  128, 512>(s4, s5, g_r5, bx, by, tid); __syncthreads();
    restr_step< 4,  8,  2,  4,   64, 512>(s5, s6, g_r6, bx, by, tid); __syncthreads();
    restr_step< 2,  4,  1,  1,   32, 512>(s6, s6, g_r7, bx, by, tid);
}

// ---------------------------------------------------------------------------
// correction level in smem (thread stride 512)
// ---------------------------------------------------------------------------
template<int TC, int NL>
static __device__ __forceinline__ void correct_level(const float* __restrict__ rL,
                                                     const float* par, float* dst,
                                                     int bx, int by, int tid) {
    const int T  = TC + 2;
    const int TP = TC / 2 + 2;
    const int Or = by * TC - 1, Oc = bx * TC - 1;
    const int Pr = by * (TC / 2) - 1, Pc = bx * (TC / 2) - 1;
    #pragma unroll 1
    for (int idx = tid; idx < T * T; idx += 512) {
        int Ii = idx / T, Jj = idx - Ii * T;
        int I = Or + Ii, J = Oc + Jj;
        float e = 0.0f;
        if (I >= 0 && I < NL && J >= 0 && J < NL) {
            int pc = (J >> 1) - Pc;
            int pr = (I >> 1) - Pr;
            float up = (I > 0)      ? par[(((I - 1) >> 1) - Pr) * TP + pc] : 0.0f;
            float dn = (I < NL - 1) ? par[(((I + 1) >> 1) - Pr) * TP + pc] : 0.0f;
            float lf = (J > 0)      ? par[pr * TP + (((J - 1) >> 1) - Pc)] : 0.0f;
            float rt = (J < NL - 1) ? par[pr * TP + (((J + 1) >> 1) - Pc)] : 0.0f;
            e = __ldg(rL + I * NL + J) - CW * (up - dn) - CW * (lf - rt);
        }
        dst[idx] = e;
    }
}

// ---------------------------------------------------------------------------
// k_e1: e1 chain. Per block, 64x64 e1 tile. Grid (32,32), 512 threads.
// ---------------------------------------------------------------------------
__global__ __launch_bounds__(512) void k_e1() {
    __shared__ float sr7[32 * 32];
    __shared__ float s8 [16 * 16];
    __shared__ float s9 [ 8 *  8];
    __shared__ float e8s[16 * 16];
    __shared__ float se7[ 3 *  3];
    __shared__ float se6[ 4 *  4];
    __shared__ float se5[ 6 *  6];
    __shared__ float se4[10 * 10];
    __shared__ float se3[18 * 18];
    __shared__ float se2[34 * 34];

    int tid = threadIdx.x;
    int bx = blockIdx.x, by = blockIdx.y;

    if (tid < 256) ((float4*)sr7)[tid] = __ldg((const float4*)g_r7 + tid);
    __syncthreads();
    if (tid < 256) {
        int I = tid >> 4, J = tid & 15;
        const float* p = sr7 + (2 * I) * 32 + 2 * J;
        s8[tid] = 0.25f * (p[0] + p[1] + p[32] + p[33]);
    }
    __syncthreads();
    if (tid < 64) {
        int I = tid >> 3, J = tid & 7;
        const float* p = s8 + (2 * I) * 16 + 2 * J;
        s9[tid] = 0.25f * (p[0] + p[1] + p[16] + p[17]);
    }
    __syncthreads();
    if (tid < 256) {
        int I = tid >> 4, J = tid & 15;
        float up = (I > 0)  ? s9[((I - 1) >> 1) * 8 + (J >> 1)] : 0.0f;
        float dn = (I < 15) ? s9[((I + 1) >> 1) * 8 + (J >> 1)] : 0.0f;
        float lf = (J > 0)  ? s9[(I >> 1) * 8 + ((J - 1) >> 1)] : 0.0f;
        float rt = (J < 15) ? s9[(I >> 1) * 8 + ((J + 1) >> 1)] : 0.0f;
        e8s[tid] = s8[tid] - CW * (up - dn) - CW * (lf - rt);
    }
    __syncthreads();
    if (tid < 9) {
        int I = by - 1 + tid / 3, J = bx - 1 + tid % 3;
        float e = 0.0f;
        if (I >= 0 && I < 32 && J >= 0 && J < 32) {
            float up = (I > 0)  ? e8s[((I - 1) >> 1) * 16 + (J >> 1)] : 0.0f;
            float dn = (I < 31) ? e8s[((I + 1) >> 1) * 16 + (J >> 1)] : 0.0f;
            float lf = (J > 0)  ? e8s[(I >> 1) * 16 + ((J - 1) >> 1)] : 0.0f;
            float rt = (J < 31) ? e8s[(I >> 1) * 16 + ((J + 1) >> 1)] : 0.0f;
            e = sr7[I * 32 + J] - CW * (up - dn) - CW * (lf - rt);
        }
        se7[tid] = e;
    }
    __syncthreads();

    correct_level< 2,   64>(g_r6, se7, se6, bx, by, tid); __syncthreads();
    correct_level< 4,  128>(g_r5, se6, se5, bx, by, tid); __syncthreads();
    correct_level< 8,  256>(g_r4, se5, se4, bx, by, tid); __syncthreads();
    correct_level<16,  512>(g_r3, se4, se3, bx, by, tid); __syncthreads();
    correct_level<32, 1024>(g_r2, se3, se2, bx, by, tid); __syncthreads();

    // final level, float4; r1 loaded evict-first (dead after this kernel)
    const int Pr = by * 32 - 1, Pc = bx * 32 - 1;
    #pragma unroll
    for (int t0 = 0; t0 < 1024; t0 += 512) {
        int t = t0 + tid;
        int Ii = t >> 4, Jq = t & 15;
        int I  = (by << 6) + Ii;
        int J0 = (bx << 6) + (Jq << 2);
        float4 r = __ldcs((const float4*)(g_r1 + (size_t)I * 2048 + J0));

        int pc0 = (J0 >> 1) - Pc;
        int mr  = (I >> 1) - Pr;
        int ur  = ((I - 1) >> 1) - Pr;
        int dr  = ((I + 1) >> 1) - Pr;
        const float* Sm = se2 + mr * 34;

        float u0 = 0.0f, u1 = 0.0f, d0 = 0.0f, d1 = 0.0f;
        if (I > 0)    { u0 = se2[ur * 34 + pc0]; u1 = se2[ur * 34 + pc0 + 1]; }
        if (I < 2047) { d0 = se2[dr * 34 + pc0]; d1 = se2[dr * 34 + pc0 + 1]; }
        float m_1 = (J0 > 0)        ? Sm[pc0 - 1] : 0.0f;
        float m0  = Sm[pc0];
        float m1  = Sm[pc0 + 1];
        float m2  = (J0 + 3 < 2047) ? Sm[pc0 + 2] : 0.0f;

        float4 e;
        e.x = r.x - CW * (u0 - d0) - CW * (m_1 - m0);
        e.y = r.y - CW * (u0 - d0) - CW * (m0  - m1);
        e.z = r.z - CW * (u1 - d1) - CW * (m0  - m1);
        e.w = r.w - CW * (u1 - d1) - CW * (m1  - m2);
        *(float4*)(g_e1 + (size_t)I * 2048 + J0) = e;
    }
}

// ---------------------------------------------------------------------------
// k_final: pure streaming final update. Grid (4,4096), 256 threads.
// v loads evict-first (__ldcs): v is dead after this kernel; preserve L2 for
// the out-writes that next iteration's k_down will re-read.
// ---------------------------------------------------------------------------
__global__ __launch_bounds__(256) void k_final(const float* __restrict__ v,
                                               const float* __restrict__ e1,
                                               float* __restrict__ out) {
    int x = ((blockIdx.x << 8) + threadIdx.x) << 2;
    int y = blockIdx.y;
    int ym = max(y - 1, 0), yp = min(y + 1, N0 - 1);
    int xl = max(x - 1, 0), xr = min(x + 4, N0 - 1);
    int xc = x >> 1;

    float4 top = __ldcs((const float4*)(v + (size_t)ym * N0 + x));
    float4 mid = __ldcs((const float4*)(v + (size_t)y  * N0 + x));
    float4 bot = __ldcs((const float4*)(v + (size_t)yp * N0 + x));
    float  lf  = __ldcs(v + (size_t)y * N0 + xl);
    float  rt  = __ldcs(v + (size_t)y * N0 + xr);

    const float* et = e1 + (ym >> 1) * 2048;
    const float* em = e1 + (y  >> 1) * 2048;
    const float* eb = e1 + (yp >> 1) * 2048;
    float2 e_t = __ldg((const float2*)(et + xc));
    float2 e_m = __ldg((const float2*)(em + xc));
    float2 e_b = __ldg((const float2*)(eb + xc));
    float  emL = __ldg(em + (xl >> 1));
    float  emR = __ldg(em + (xr >> 1));

    float4 o;
    o.x = -CW * ((top.x - e_t.x) - (bot.x - e_b.x)) - CW * ((lf    - emL)   - (mid.y - e_m.x));
    o.y = -CW * ((top.y - e_t.x) - (bot.y - e_b.x)) - CW * ((mid.x - e_m.x) - (mid.z - e_m.y));
    o.z = -CW * ((top.z - e_t.y) - (bot.z - e_b.y)) - CW * ((mid.y - e_m.x) - (mid.w - e_m.y));
    o.w = -CW * ((top.w - e_t.y) - (bot.w - e_b.y)) - CW * ((mid.z - e_m.y) - (rt    - emR));
    *(float4*)(out + (size_t)y * N0 + x) = o;
}

// ---------------------------------------------------------------------------
extern "C" void kernel_launch(void* const* d_in, const int* in_sizes, int n_in,
                              void* d_out, int out_size) {
    const float* u = (const float*)d_in[0];
    float* out = (float*)d_out;

    float *pv, *pe1;
    cudaGetSymbolAddress((void**)&pv,  g_v);
    cudaGetSymbolAddress((void**)&pe1, g_e1);

    const dim3 G(32, 32);
    const dim3 GF(4, 4096);
    const float* vin[4]  = { u,   pv,  out, pv  };
    float*       vout[4] = { pv,  out, pv,  out };

    for (int it = 0; it < 4; ++it) {
        k_down<<<G, 512>>>(vin[it]);
        k_e1<<<G, 512>>>();
        k_final<<<GF, 256>>>(vin[it], pe1, vout[it]);
    }
}